// round 4
// baseline (speedup 1.0000x reference)
#include <cuda_runtime.h>

namespace {

constexpr int Bn = 256;
constexpr int Dn = 256;
constexpr int Nn = 1024;
constexpr float EPS_NORM = 1e-12f;
constexpr float EPS_DIV  = 1e-5f;

// Block-wide sum over 1024 threads (32 warps). All threads must call.
__device__ __forceinline__ float block_reduce(float val, float* red) {
#pragma unroll
    for (int o = 16; o; o >>= 1) val += __shfl_down_sync(0xffffffffu, val, o);
    const int lane = threadIdx.x & 31;
    const int wid  = threadIdx.x >> 5;
    if (lane == 0) red[wid] = val;
    __syncthreads();
    if (wid == 0) {
        val = red[lane];
#pragma unroll
        for (int o = 16; o; o >>= 1) val += __shfl_down_sync(0xffffffffu, val, o);
        if (lane == 0) red[0] = val;
    }
    __syncthreads();
    float r = red[0];
    __syncthreads();   // protect red[] for the next call
    return r;
}

__global__ __launch_bounds__(1024, 1) void svpn_kernel(
    const float* __restrict__ x,       // (B, D, N)
    const float* __restrict__ weight,  // (D,)
    float* __restrict__ out)           // (B, D*N)
{
    __shared__ float v[Dn];    // current right vector (unnormalized scale ok at init)
    __shared__ float v1[Dn];   // component-1 right vector
    __shared__ float zb[Dn];   // z = A^T u scratch
    __shared__ float u[Nn];    // current left vector (ends as u2)
    __shared__ float u1[Nn];   // component-1 left vector
    __shared__ float red[32];
    __shared__ float sS[2];    // spectral values s1, s2

    const int tid = threadIdx.x;
    const int b   = blockIdx.x;
    const float* xb = x + (size_t)b * Dn * Nn;

    if (tid < Dn) v[tid] = weight[tid];
    __syncthreads();

    for (int sv = 0; sv < 2; ++sv) {
        const float s1 = (sv == 1) ? sS[0] : 0.f;
        for (int it = 0; it < 3; ++it) {
            // ---- deflation dot (v1 . v) before u-pass ----
            float dvv = 0.f;
            if (sv == 1) {
                float p = (tid < Dn) ? v1[tid] * v[tid] : 0.f;
                dvv = block_reduce(p, red);
            }

            // ---- u-pass: w[n] = sum_d x[d,n] * v[d]   (thread per n, coalesced) ----
            float acc = 0.f;
            const float* xp = xb + tid;  // n = tid
#pragma unroll 8
            for (int d = 0; d < Dn; ++d)
                acc = fmaf(xp[(size_t)d * Nn], v[d], acc);
            if (sv == 1) acc -= s1 * dvv * u1[tid];

            float ss  = block_reduce(acc * acc, red);
            float inv = 1.f / fmaxf(sqrtf(ss), EPS_NORM);
            u[tid] = acc * inv;
            __syncthreads();

            // ---- deflation dot (u1 . u) before v-pass ----
            float duu = 0.f;
            if (sv == 1) duu = block_reduce(u1[tid] * u[tid], red);

            // ---- v-pass: z[d] = sum_n x[d,n] * u[n]   (warp per row, float4) ----
            {
                const int wid  = tid >> 5;
                const int lane = tid & 31;
                const float4* u4 = reinterpret_cast<const float4*>(u);
#pragma unroll
                for (int r = 0; r < 8; ++r) {
                    const int d = wid * 8 + r;
                    const float4* row =
                        reinterpret_cast<const float4*>(xb + (size_t)d * Nn);
                    float racc = 0.f;
#pragma unroll
                    for (int j = 0; j < 8; ++j) {
                        const int i = lane + 32 * j;
                        float4 xv = row[i];
                        float4 uv = u4[i];
                        racc += xv.x * uv.x + xv.y * uv.y + xv.z * uv.z + xv.w * uv.w;
                    }
#pragma unroll
                    for (int o = 16; o; o >>= 1)
                        racc += __shfl_down_sync(0xffffffffu, racc, o);
                    if (lane == 0) zb[d] = racc;
                }
            }
            __syncthreads();

            // ---- normalize z -> v ;  s = ||z|| on last iteration ----
            float zv = 0.f;
            if (tid < Dn) {
                zv = zb[tid];
                if (sv == 1) zv -= s1 * duu * v1[tid];
            }
            float zz   = block_reduce(zv * zv, red);
            float nrm  = sqrtf(zz);
            float zinv = 1.f / fmaxf(nrm, EPS_NORM);
            if (tid < Dn) v[tid] = zv * zinv;
            if (tid == 0 && it == 2) sS[sv] = nrm;
            __syncthreads();
        }
        if (sv == 0) {
            u1[tid] = u[tid];
            if (tid < Dn) {
                v1[tid] = v[tid];
                v[tid]  = weight[tid];   // reset for second component
            }
            __syncthreads();
        }
    }

    // ---- final fused output:
    // out[d,n] = c*x[d,n] + (sqrt(s1)-s1*c)*u1[n]*v1[d] + (sqrt(s2)-s2*c)*u2[n]*v2[d]
    const float s1f = sS[0], s2f = sS[1];
    const float c  = 1.f / (sqrtf(s2f) + EPS_DIV);
    const float c1 = sqrtf(s1f) - s1f * c;
    const float c2 = sqrtf(s2f) - s2f * c;

    const float4* x4  = reinterpret_cast<const float4*>(xb);
    float4*       o4  = reinterpret_cast<float4*>(out + (size_t)b * Dn * Nn);
    const float4* u14 = reinterpret_cast<const float4*>(u1);
    const float4* u24 = reinterpret_cast<const float4*>(u);  // u holds u2

    constexpr int TOT4 = Dn * Nn / 4;       // 65536
#pragma unroll 4
    for (int idx = tid; idx < TOT4; idx += 1024) {
        const int d   = idx >> 8;           // Nn/4 = 256 float4 per row
        const int col = idx & 255;
        const float a1 = c1 * v1[d];
        const float a2 = c2 * v[d];        // v holds v2
        const float4 xv = x4[idx];
        const float4 uA = u14[col];
        const float4 uB = u24[col];
        float4 o;
        o.x = fmaf(c, xv.x, fmaf(a1, uA.x, a2 * uB.x));
        o.y = fmaf(c, xv.y, fmaf(a1, uA.y, a2 * uB.y));
        o.z = fmaf(c, xv.z, fmaf(a1, uA.z, a2 * uB.z));
        o.w = fmaf(c, xv.w, fmaf(a1, uA.w, a2 * uB.w));
        o4[idx] = o;
    }
}

}  // namespace

extern "C" void kernel_launch(void* const* d_in, const int* in_sizes, int n_in,
                              void* d_out, int out_size) {
    const float* x = (const float*)d_in[0];
    const float* w = (const float*)d_in[1];
    // Defensive: ensure x is the big tensor, weight the small one.
    if (n_in >= 2 && in_sizes[0] < in_sizes[1]) {
        const float* t = x; x = w; w = t;
    }
    svpn_kernel<<<Bn, 1024>>>(x, w, (float*)d_out);
}

// round 11
// speedup vs baseline: 1.2490x; 1.2490x over previous
#include <cuda_runtime.h>
#include <cstdint>

namespace {

constexpr int Bn = 256, Dn = 256, Nn = 1024;
constexpr int TS = 64;                 // tile columns (n) per step
constexpr int NT = Nn / TS;            // 16 tiles
constexpr int TSTRIDE = 68;            // padded floats per tile row (16B-aligned, 17 float4s)
constexpr int TILE_FLOATS = Dn * TSTRIDE;
constexpr float EPS_NORM = 1e-12f;
constexpr float EPS_DIV  = 1e-5f;
constexpr int GRID = 128, TPB = 1024;

// shared memory layout (float offsets)
constexpr int OFF_TILE  = 0;                       // 2 * TILE_FLOATS (double buffer)
constexpr int OFF_U1    = 2 * TILE_FLOATS;         // 1024
constexpr int OFF_UCUR  = OFF_U1 + Nn;             // 1024
constexpr int OFF_V     = OFF_UCUR + Nn;           // 256
constexpr int OFF_V1    = OFF_V + Dn;              // 256
constexpr int OFF_ZRED  = OFF_V1 + Dn;             // 4*256
constexpr int OFF_WPART = OFF_ZRED + 4 * Dn;       // 16*64
constexpr int OFF_WS    = OFF_WPART + 16 * TS;     // 64
constexpr int OFF_RED   = OFF_WS + TS;             // 32
constexpr int OFF_SS    = OFF_RED + 32;            // 4
constexpr int SMEM_BYTES = (OFF_SS + 4) * 4;

__device__ __forceinline__ void cp16(void* dst_smem, const void* src) {
    unsigned d = (unsigned)__cvta_generic_to_shared(dst_smem);
    asm volatile("cp.async.cg.shared.global [%0], [%1], 16;" :: "r"(d), "l"(src));
}

// Block-wide sum over 1024 threads (32 warps). All threads must call.
__device__ __forceinline__ float block_reduce(float val, float* red) {
#pragma unroll
    for (int o = 16; o; o >>= 1) val += __shfl_down_sync(0xffffffffu, val, o);
    const int lane = threadIdx.x & 31;
    const int wid  = threadIdx.x >> 5;
    if (lane == 0) red[wid] = val;
    __syncthreads();
    if (wid == 0) {
        val = red[lane];
#pragma unroll
        for (int o = 16; o; o >>= 1) val += __shfl_down_sync(0xffffffffu, val, o);
        if (lane == 0) red[0] = val;
    }
    __syncthreads();
    float r = red[0];
    __syncthreads();
    return r;
}

__global__ __launch_bounds__(TPB, 1) void svpn_kernel(
    const float* __restrict__ x,       // (B, D, N)
    const float* __restrict__ weight,  // (D,)
    float* __restrict__ out)           // (B, D*N)
{
    extern __shared__ float sm[];
    float* tile  = sm + OFF_TILE;
    float* u1    = sm + OFF_U1;    // normalized u of component 1
    float* ucur  = sm + OFF_UCUR;  // unnormalized w of current pass (ends as u2)
    float* vv    = sm + OFF_V;     // current v
    float* v1    = sm + OFF_V1;    // final v of component 1
    float* zred  = sm + OFF_ZRED;
    float* wpart = sm + OFF_WPART;
    float* ws    = sm + OFF_WS;
    float* red   = sm + OFF_RED;
    float* sS    = sm + OFF_SS;

    const int tid = threadIdx.x;
    const int d_z = tid & 255;         // z-phase: output row
    const int g_z = tid >> 8;          // z-phase: n quarter (0..3)
    const int g2  = tid >> 6;          // w-phase: d group (0..15)
    const int n_w = tid & 63;          // w-phase: column within tile

    for (int b = blockIdx.x; b < Bn; b += gridDim.x) {
        const float* xb = x + (size_t)b * (Dn * Nn);
        if (tid < Dn) vv[tid] = weight[tid];
        __syncthreads();
        float s1 = 0.f;

        for (int sv = 0; sv < 2; ++sv) {
            for (int it = 0; it < 3; ++it) {
                // deflation scalar for the w-side: s1 * (v1 . v)
                float c_u = 0.f;
                if (sv) {
                    float p = (tid < Dn) ? v1[tid] * vv[tid] : 0.f;
                    c_u = s1 * block_reduce(p, red);
                }
                // cache this thread's 16 v entries for the w phase
                float vreg[16];
#pragma unroll
                for (int i = 0; i < 16; ++i) vreg[i] = vv[g2 * 16 + i];

                float zacc = 0.f;

                // prefetch tile 0
#pragma unroll
                for (int k = 0; k < 4; ++k) {
                    int id = tid + k * TPB;
                    int d = id >> 4, c4 = id & 15;
                    cp16(tile + d * TSTRIDE + c4 * 4, xb + (size_t)d * Nn + c4 * 4);
                }
                asm volatile("cp.async.commit_group;");

                for (int t = 0; t < NT; ++t) {
                    float* tl = tile + (t & 1) * TILE_FLOATS;
                    if (t + 1 < NT) {
                        float* st = tile + ((t + 1) & 1) * TILE_FLOATS;
#pragma unroll
                        for (int k = 0; k < 4; ++k) {
                            int id = tid + k * TPB;
                            int d = id >> 4, c4 = id & 15;
                            cp16(st + d * TSTRIDE + c4 * 4,
                                 xb + (size_t)d * Nn + (t + 1) * TS + c4 * 4);
                        }
                        asm volatile("cp.async.commit_group;");
                        asm volatile("cp.async.wait_group 1;");
                    } else {
                        asm volatile("cp.async.wait_group 0;");
                    }
                    __syncthreads();

                    // w phase: partial w[n] over this thread's 16 d's (conflict-free LDS)
                    {
                        const float* tcol = tl + (g2 * 16) * TSTRIDE + n_w;
                        float wp = 0.f;
#pragma unroll
                        for (int i = 0; i < 16; ++i)
                            wp = fmaf(tcol[i * TSTRIDE], vreg[i], wp);
                        wpart[g2 * TS + n_w] = wp;
                    }
                    __syncthreads();

                    // reduce w across the 16 d-groups; apply u-side deflation; persist
                    if (tid < TS) {
                        float w = 0.f;
#pragma unroll
                        for (int g = 0; g < 16; ++g) w += wpart[g * TS + tid];
                        if (sv) w -= c_u * u1[t * TS + tid];
                        ws[tid] = w;
                        ucur[t * TS + tid] = w;
                    }
                    __syncthreads();

                    // z phase: zacc += sum_{n in quarter} tile[d][n] * w[n]  (float4, conflict-free)
                    {
                        const float4* t4 = reinterpret_cast<const float4*>(tl);
                        const float4* w4 = reinterpret_cast<const float4*>(ws);
                        const int base = d_z * 17 + g_z * 4;
#pragma unroll
                        for (int j = 0; j < 4; ++j) {
                            float4 a = t4[base + j];
                            float4 wv = w4[g_z * 4 + j];
                            zacc = fmaf(a.x, wv.x,
                                   fmaf(a.y, wv.y,
                                   fmaf(a.z, wv.z,
                                   fmaf(a.w, wv.w, zacc))));
                        }
                    }
                    __syncthreads();
                }  // tiles

                // pass statistics
                float wv_ = ucur[tid];
                float ww = block_reduce(wv_ * wv_, red);           // ||w||^2
                float uwr = 0.f;
                if (sv) uwr = block_reduce(u1[tid] * wv_, red);    // u1 . w

                zred[tid] = zacc;
                __syncthreads();
                float zd = 0.f;
                if (tid < Dn) {
                    zd = zred[tid] + zred[Dn + tid] + zred[2 * Dn + tid] + zred[3 * Dn + tid];
                    if (sv) zd -= s1 * uwr * v1[tid];              // z-side deflation
                }
                float zz = block_reduce((tid < Dn) ? zd * zd : 0.f, red);
                float nz = sqrtf(zz);
                if (tid < Dn) vv[tid] = zd / fmaxf(nz, EPS_NORM);

                if (it == 2) {
                    float nwv  = fmaxf(sqrtf(ww), EPS_NORM);
                    float sval = nz / nwv;          // s = ||A^T u|| for this component
                    float invw = 1.f / nwv;
                    if (sv == 0) {
                        u1[tid] = ucur[tid] * invw;
                        if (tid < Dn) v1[tid] = zd / fmaxf(nz, EPS_NORM);
                        if (tid == 0) sS[0] = sval;
                    } else {
                        ucur[tid] *= invw;          // ucur becomes u2
                        if (tid == 0) sS[1] = sval;
                    }
                }
                __syncthreads();
            }  // it

            if (sv == 0) {
                s1 = sS[0];
                if (tid < Dn) vv[tid] = weight[tid];  // reset for component 2
                __syncthreads();
            }
        }  // sv

        // fused output:
        // out = c*x + (sqrt(s1)-s1*c)*u1 v1^T + (sqrt(s2)-s2*c)*u2 v2^T,  c = 1/(sqrt(s2)+eps)
        const float s1f = sS[0], s2f = sS[1];
        const float c  = 1.f / (sqrtf(s2f) + EPS_DIV);
        const float c1 = sqrtf(s1f) - s1f * c;
        const float c2 = sqrtf(s2f) - s2f * c;

        const float4* x4  = reinterpret_cast<const float4*>(xb);
        float4*       o4  = reinterpret_cast<float4*>(out + (size_t)b * (Dn * Nn));
        const float4* u14 = reinterpret_cast<const float4*>(u1);
        const float4* u24 = reinterpret_cast<const float4*>(ucur);  // u2

        constexpr int TOT4 = Dn * Nn / 4;  // 65536
#pragma unroll 4
        for (int idx = tid; idx < TOT4; idx += TPB) {
            const int d   = idx >> 8;
            const int col = idx & 255;
            const float a1 = c1 * v1[d];
            const float a2 = c2 * vv[d];   // vv holds v2
            const float4 xv = __ldcs(&x4[idx]);
            const float4 uA = u14[col];
            const float4 uB = u24[col];
            float4 o;
            o.x = fmaf(c, xv.x, fmaf(a1, uA.x, a2 * uB.x));
            o.y = fmaf(c, xv.y, fmaf(a1, uA.y, a2 * uB.y));
            o.z = fmaf(c, xv.z, fmaf(a1, uA.z, a2 * uB.z));
            o.w = fmaf(c, xv.w, fmaf(a1, uA.w, a2 * uB.w));
            __stcs(&o4[idx], o);
        }
        __syncthreads();  // protect smem before next batch
    }  // batch loop
}

}  // namespace

extern "C" void kernel_launch(void* const* d_in, const int* in_sizes, int n_in,
                              void* d_out, int out_size) {
    const float* x = (const float*)d_in[0];
    const float* w = (const float*)d_in[1];
    if (n_in >= 2 && in_sizes[0] < in_sizes[1]) {
        const float* t = x; x = w; w = t;
    }
    cudaFuncSetAttribute(svpn_kernel, cudaFuncAttributeMaxDynamicSharedMemorySize,
                         SMEM_BYTES);
    svpn_kernel<<<GRID, TPB, SMEM_BYTES>>>(x, w, (float*)d_out);
}